// round 15
// baseline (speedup 1.0000x reference)
#include <cuda_runtime.h>
#include <cstdint>

// out[b,c,h,w] = x[b,c,2h,2w] * 0.5f     (Haar DWT subband sum collapses to this)
// x:  [16, 64, 512, 512] fp32,  out: [16, 64, 256, 256] fp32
//
// R14 = R8 configuration with ONE change: default (caching) loads instead of
// __ldcs — the last untested one-variable cell in the optimization matrix.
//   - flat grid, 32768 blocks x 256 threads, each block owns 1024 aligned pairs
//   - MLP=4: thread t handles pairs base+t+{0,256,512,768}
//   - single index decomposition; in_idx_k = a0 + 512k (rows r,r+2,r+4,r+6)
//   - __stcs stores (proven better than default in R9 isolation)
//   - fully warp-coalesced: LDG.128 spans 512B/warp, STG.64 spans 256B/warp
//
// Geometry:
//   pair index p in [0, 33'554'432):  out float2 index = p
//   pair = p & 127, orow = (p>>7) & 255, bc = p >> 15
//   input float4 index = bc*65536 + orow*256 + pair   (even input row 2*orow)

__global__ __launch_bounds__(256) void haar_sum_kernel(
    const float4* __restrict__ x, float2* __restrict__ out)
{
    const unsigned i0 = blockIdx.x * 1024u + threadIdx.x;

    // single index decomposition
    const unsigned pair = i0 & 127u;
    const unsigned orow = (i0 >> 7) & 255u;
    const unsigned bc   = i0 >> 15;
    const long long a0  = ((long long)bc << 16) + ((long long)orow << 8) + pair;

    // four independent default-policy loads (rows r, r+2, r+4, r+6)
    float4 v0 = x[a0];
    float4 v1 = x[a0 +  512];
    float4 v2 = x[a0 + 1024];
    float4 v3 = x[a0 + 1536];

    float2 o0, o1, o2, o3;
    o0.x = v0.x * 0.5f;  o0.y = v0.z * 0.5f;
    o1.x = v1.x * 0.5f;  o1.y = v1.z * 0.5f;
    o2.x = v2.x * 0.5f;  o2.y = v2.z * 0.5f;
    o3.x = v3.x * 0.5f;  o3.y = v3.z * 0.5f;

    // streaming stores (proven optimal in R9 isolation)
    __stcs(&out[i0],        o0);
    __stcs(&out[i0 + 256u], o1);
    __stcs(&out[i0 + 512u], o2);
    __stcs(&out[i0 + 768u], o3);
}

extern "C" void kernel_launch(void* const* d_in, const int* in_sizes, int n_in,
                              void* d_out, int out_size)
{
    const float4* x = (const float4*)d_in[0];
    float2* out     = (float2*)d_out;

    // out_size = 67,108,864 floats -> 33,554,432 pairs -> 1024 pairs per block
    long long n_pairs = (long long)out_size / 2;
    long long blocks  = n_pairs / 1024;                // 32768

    haar_sum_kernel<<<(unsigned)blocks, 256>>>(x, out);
}

// round 16
// speedup vs baseline: 1.0049x; 1.0049x over previous
#include <cuda_runtime.h>
#include <cstdint>

// out[b,c,h,w] = x[b,c,2h,2w] * 0.5f     (Haar DWT subband sum collapses to this:
//   LL+LH+HL+HH = 2*x[0::2,0::2], divided by 4 -> 0.5*x[0::2,0::2])
// x:  [16, 64, 512, 512] fp32,  out: [16, 64, 256, 256] fp32
//
// FINAL — best of 11 measured variants (full one-variable matrix explored):
//   - flat grid, 32768 blocks x 256 threads, each block owns 1024 aligned pairs
//   - MLP=4 front-batched independent loads (1->2 +13%, 2->4 +2%, 4->8 neutral)
//   - per-thread span 16B; wider spans destroy warp coalescing (L1 96% blowup)
//   - flat grid beats persistent loop (fresh CTAs keep load queues deep)
//   - __ldcs loads (policy neutral) + __stcs stores (+2% vs write-back)
//   - single index decomposition (alu 9.5% -> 3.5%); in_idx_k = a0 + 512k
//   - fully warp-coalesced: LDG.128 = 512B/warp, STG.64 = 256B/warp
//
// Geometry:
//   pair index p in [0, 33'554'432):  out float2 index = p
//   pair = p & 127, orow = (p>>7) & 255, bc = p >> 15
//   input float4 index = bc*65536 + orow*256 + pair   (even input row 2*orow)
//
// Measured: 6.96 TB/s HBM (87.8% of spec), ncu-dur 108.9us. Traffic is at the
// algorithmic floor (512 MiB read of even rows + 256 MiB write); the kernel is
// pinned at the HBM controller's 2:1 read/write + skip-alternate-2KB-row
// turnaround ceiling. No tested kernel-side lever moves it.

__global__ __launch_bounds__(256) void haar_sum_kernel(
    const float4* __restrict__ x, float2* __restrict__ out)
{
    const unsigned i0 = blockIdx.x * 1024u + threadIdx.x;

    // single index decomposition (bc/orow cannot wrap in an aligned 1024-pair block)
    const unsigned pair = i0 & 127u;
    const unsigned orow = (i0 >> 7) & 255u;
    const unsigned bc   = i0 >> 15;
    const long long a0  = ((long long)bc << 16) + ((long long)orow << 8) + pair;

    // four independent streaming loads (input rows r, r+2, r+4, r+6)
    float4 v0 = __ldcs(&x[a0]);
    float4 v1 = __ldcs(&x[a0 +  512]);
    float4 v2 = __ldcs(&x[a0 + 1024]);
    float4 v3 = __ldcs(&x[a0 + 1536]);

    float2 o0, o1, o2, o3;
    o0.x = v0.x * 0.5f;  o0.y = v0.z * 0.5f;
    o1.x = v1.x * 0.5f;  o1.y = v1.z * 0.5f;
    o2.x = v2.x * 0.5f;  o2.y = v2.z * 0.5f;
    o3.x = v3.x * 0.5f;  o3.y = v3.z * 0.5f;

    // streaming stores: avoid dirty-line write-back interference in L2
    __stcs(&out[i0],        o0);
    __stcs(&out[i0 + 256u], o1);
    __stcs(&out[i0 + 512u], o2);
    __stcs(&out[i0 + 768u], o3);
}

extern "C" void kernel_launch(void* const* d_in, const int* in_sizes, int n_in,
                              void* d_out, int out_size)
{
    const float4* x = (const float4*)d_in[0];
    float2* out     = (float2*)d_out;

    // out_size = 67,108,864 floats -> 33,554,432 pairs -> 1024 pairs per block
    long long n_pairs = (long long)out_size / 2;
    long long blocks  = n_pairs / 1024;                // 32768

    haar_sum_kernel<<<(unsigned)blocks, 256>>>(x, out);
}

// round 17
// speedup vs baseline: 1.0101x; 1.0052x over previous
#include <cuda_runtime.h>
#include <cstdint>

// out[b,c,h,w] = x[b,c,2h,2w] * 0.5f     (Haar DWT subband sum collapses to this:
//   LL+LH+HL+HH = 2*x[0::2,0::2], divided by 4 -> 0.5*x[0::2,0::2])
// x:  [16, 64, 512, 512] fp32,  out: [16, 64, 256, 256] fp32
//
// R16 = proven-optimal config with 128-thread blocks (finer CTA granularity:
// more independent CTA fronts per SM, smoother load injection, smaller tail):
//   - flat grid, 65536 blocks x 128 threads, each block owns 512 aligned pairs
//   - MLP=4: thread t handles pairs base+t+{0,128,256,384}
//   - +128 pairs = +1 output row = +2 input rows = +256 float4, so
//     in_idx_k = a0 + 256k (single decomposition, immediate offsets)
//   - __ldcs loads + __stcs stores (proven in isolation)
//   - fully warp-coalesced: LDG.128 = 512B/warp, STG.64 = 256B/warp
//
// Geometry:
//   pair index p in [0, 33'554'432):  out float2 index = p
//   pair = p & 127, orow = (p>>7) & 255, bc = p >> 15
//   input float4 index = bc*65536 + orow*256 + pair   (even input row 2*orow)
//   bc/orow cannot wrap within an aligned 512-pair block.

__global__ __launch_bounds__(128) void haar_sum_kernel(
    const float4* __restrict__ x, float2* __restrict__ out)
{
    const unsigned i0 = blockIdx.x * 512u + threadIdx.x;

    // single index decomposition
    const unsigned pair = i0 & 127u;
    const unsigned orow = (i0 >> 7) & 255u;
    const unsigned bc   = i0 >> 15;
    const long long a0  = ((long long)bc << 16) + ((long long)orow << 8) + pair;

    // four independent streaming loads (input rows r, r+2, r+4, r+6)
    float4 v0 = __ldcs(&x[a0]);
    float4 v1 = __ldcs(&x[a0 + 256]);
    float4 v2 = __ldcs(&x[a0 + 512]);
    float4 v3 = __ldcs(&x[a0 + 768]);

    float2 o0, o1, o2, o3;
    o0.x = v0.x * 0.5f;  o0.y = v0.z * 0.5f;
    o1.x = v1.x * 0.5f;  o1.y = v1.z * 0.5f;
    o2.x = v2.x * 0.5f;  o2.y = v2.z * 0.5f;
    o3.x = v3.x * 0.5f;  o3.y = v3.z * 0.5f;

    // streaming stores: avoid dirty-line write-back interference in L2
    __stcs(&out[i0],        o0);
    __stcs(&out[i0 + 128u], o1);
    __stcs(&out[i0 + 256u], o2);
    __stcs(&out[i0 + 384u], o3);
}

extern "C" void kernel_launch(void* const* d_in, const int* in_sizes, int n_in,
                              void* d_out, int out_size)
{
    const float4* x = (const float4*)d_in[0];
    float2* out     = (float2*)d_out;

    // out_size = 67,108,864 floats -> 33,554,432 pairs -> 512 pairs per block
    long long n_pairs = (long long)out_size / 2;
    long long blocks  = n_pairs / 512;                 // 65536

    haar_sum_kernel<<<(unsigned)blocks, 128>>>(x, out);
}